// round 14
// baseline (speedup 1.0000x reference)
#include <cuda_runtime.h>
#include <cuda_fp16.h>
#include <math.h>
#include <stdint.h>

// ---------------- problem constants ----------------
#define T_TOK   2048
#define DDIM    768
#define HDIM    1536
#define NEXP    16
#define NSLOT   4
#define TOTSLOT (T_TOK*NSLOT)
#define LN_EPS  1e-5f

#define IX_X    0
#define IX_GW   1
#define IX_GB   2
#define IX_F1W  3
#define IX_F1B  4
#define IX_LNW  5
#define IX_LNB  6
#define IX_F2W  7
#define IX_F2B  8

// ---------------- device scratch ----------------
__device__ const float* g_p[9];
__device__ int   g_ecnt[NEXP];
__device__ int   g_elist[NEXP * T_TOK];
__device__ __align__(16) float  g_wslot[TOTSLOT];
__device__ int   g_eslot[TOTSLOT];
__device__ __align__(16) __half g_hh[(size_t)TOTSLOT * HDIM];            // fc1 out / LN out (fp16)
__device__ __align__(16) float  g_ybuf[(size_t)TOTSLOT * DDIM];          // fc2 out fp32
__device__ __align__(16) __half g_xh[(size_t)T_TOK * DDIM];              // x fp16
__device__ __align__(16) __half g_w1h[(size_t)NEXP * DDIM * HDIM];
__device__ __align__(16) __half g_w2h[(size_t)NEXP * HDIM * DDIM];

struct InArgs { const float* p[9]; int sz[9]; int n; };

#define WQUARTS (NEXP * DDIM * HDIM / 4)      // 4,718,592 float4s per weight
#define XQUARTS (T_TOK * DDIM / 4)            // 393,216

__device__ __forceinline__ uint2 f4_to_h4(float4 v) {
    __half2 lo = __floats2half2_rn(v.x, v.y);
    __half2 hi = __floats2half2_rn(v.z, v.w);
    return make_uint2(*(uint32_t*)&lo, *(uint32_t*)&hi);
}

// ---------------- classify inputs (warp-parallel value scans) ----------------
__global__ void classify_kernel(InArgs a) {
    int lane = threadIdx.x;
    if (lane < NEXP) g_ecnt[lane] = 0;

    __shared__ int nzf[9], onesf[9];
    for (int i = 0; i < 9; i++) {
        bool nz = false, ones = true;
        if (i < a.n) {
            for (int j = lane; j < 256; j += 32)
                if (a.p[i][j] != 0.f) { nz = true; break; }
            for (int j = lane; j < 64; j += 32)
                if (a.p[i][j] != 1.0f) { ones = false; break; }
        }
        unsigned nzb = __ballot_sync(0xffffffffu, nz);
        unsigned onb = __ballot_sync(0xffffffffu, !ones);
        if (lane == 0) { nzf[i] = (nzb != 0); onesf[i] = (onb == 0); }
    }
    __syncwarp();
    if (lane != 0) return;

    bool used[9]; const float* P[9];
#pragma unroll
    for (int i = 0; i < 9; i++) { used[i] = false; P[i] = nullptr; }

    for (int i = 0; i < a.n && i < 9; i++) {
        if (a.sz[i] == T_TOK * DDIM)      { P[IX_X]  = a.p[i]; used[i] = true; }
        else if (a.sz[i] == NEXP)         { P[IX_GB] = a.p[i]; used[i] = true; }
    }
    for (int i = 0; i < a.n && i < 9; i++) {
        if (!used[i] && a.sz[i] == NEXP * DDIM * HDIM) {
            if (!P[IX_F1W]) P[IX_F1W] = a.p[i]; else P[IX_F2W] = a.p[i];
            used[i] = true;
        }
    }
    for (int i = 0; i < a.n && i < 9; i++) {
        if (!used[i] && a.sz[i] == DDIM * NEXP) {
            if (nzf[i] && !P[IX_GW]) P[IX_GW] = a.p[i];
            else if (!P[IX_F2B])     P[IX_F2B] = a.p[i];
            else                     P[IX_GW]  = a.p[i];
            used[i] = true;
        }
    }
    for (int i = 0; i < a.n && i < 9; i++) {
        if (!used[i] && a.sz[i] == NEXP * HDIM) {
            if (onesf[i] && !P[IX_LNW]) P[IX_LNW] = a.p[i];
            else if (!P[IX_F1B])        P[IX_F1B] = a.p[i];
            else if (!P[IX_LNB])        P[IX_LNB] = a.p[i];
            else                        P[IX_LNW] = a.p[i];
            used[i] = true;
        }
    }
#pragma unroll
    for (int k = 0; k < 9; k++) if (!P[k]) P[k] = a.p[k];
#pragma unroll
    for (int k = 0; k < 9; k++) g_p[k] = P[k];
}

// ---------------- fused gating + cvt(w1, x) ----------------
// blocks [0, 256): gating (one warp per token)
// blocks [256, 256+CVT1_BLKS): w1 -> fp16 (4 float4/thread)
// blocks [256+CVT1_BLKS, +CVTX_BLKS): x -> fp16
#define GATE_BLKS 256
#define CVT1_BLKS (WQUARTS / (256 * 4))       // 4608
#define CVTX_BLKS (XQUARTS / (256 * 4))       // 384

__global__ __launch_bounds__(256) void gate_cvt_kernel()
{
    if (blockIdx.x >= GATE_BLKS) {
        int cb = blockIdx.x - GATE_BLKS;
        if (cb < CVT1_BLKS) {
            int base = cb * 1024 + threadIdx.x;
#pragma unroll
            for (int it = 0; it < 4; it++) {
                int i = base + it * 256;
                float4 v = __ldcs((const float4*)g_p[IX_F1W] + i);
                ((uint2*)g_w1h)[i] = f4_to_h4(v);
            }
        } else {
            int base = (cb - CVT1_BLKS) * 1024 + threadIdx.x;
#pragma unroll
            for (int it = 0; it < 4; it++) {
                int i = base + it * 256;
                float4 v = ((const float4*)g_p[IX_X])[i];
                ((uint2*)g_xh)[i] = f4_to_h4(v);
            }
        }
        return;
    }

    const float* x  = g_p[IX_X];
    const float* gw = g_p[IX_GW];
    const float* gb = g_p[IX_GB];

    int gtid = blockIdx.x * blockDim.x + threadIdx.x;
    int t    = gtid >> 5;
    int lane = gtid & 31;
    if (t >= T_TOK) return;

    float acc[NEXP];
#pragma unroll
    for (int e = 0; e < NEXP; e++) acc[e] = 0.f;

    const float* xr = x + (size_t)t * DDIM;
    for (int d = lane; d < DDIM; d += 32) {
        float xv = xr[d];
        const float* wr = gw + d * NEXP;
#pragma unroll
        for (int e = 0; e < NEXP; e++) acc[e] += xv * wr[e];
    }
#pragma unroll
    for (int e = 0; e < NEXP; e++) {
#pragma unroll
        for (int off = 16; off; off >>= 1)
            acc[e] += __shfl_xor_sync(0xffffffffu, acc[e], off);
    }

    if (lane == 0) {
        float s[NEXP];
#pragma unroll
        for (int e = 0; e < NEXP; e++) s[e] = acc[e] + gb[e];
        s[0] = -1e9f;
        float mx = s[0];
#pragma unroll
        for (int e = 1; e < NEXP; e++) mx = fmaxf(mx, s[e]);
        float p[NEXP]; float sum = 0.f;
#pragma unroll
        for (int e = 0; e < NEXP; e++) { p[e] = expf(s[e] - mx); sum += p[e]; }
        float inv = 1.f / sum;
#pragma unroll
        for (int e = 0; e < NEXP; e++) p[e] *= inv;

        int base = t * NSLOT;
        g_wslot[base] = 1.0f;
        g_eslot[base] = 0;
        int pos = atomicAdd(&g_ecnt[0], 1);
        g_elist[0 * T_TOK + pos] = base;

        for (int k = 0; k < 3; k++) {
            int bi = -1; float bv = -1.f;
#pragma unroll
            for (int e = 0; e < NEXP; e++)
                if (p[e] > bv) { bv = p[e]; bi = e; }
            p[bi] = -2.f;
            g_wslot[base + 1 + k] = bv;
            g_eslot[base + 1 + k] = bi;
            int pp = atomicAdd(&g_ecnt[bi], 1);
            g_elist[bi * T_TOK + pp] = base + 1 + k;
        }
    }
}

// ---------------- fp16 MMA helpers ----------------
__device__ __forceinline__ void ldsm_x4(uint32_t& r0, uint32_t& r1, uint32_t& r2, uint32_t& r3,
                                        uint32_t addr) {
    asm volatile("ldmatrix.sync.aligned.m8n8.x4.shared.b16 {%0,%1,%2,%3}, [%4];"
                 : "=r"(r0), "=r"(r1), "=r"(r2), "=r"(r3) : "r"(addr));
}
__device__ __forceinline__ void ldsm_x4t(uint32_t& r0, uint32_t& r1, uint32_t& r2, uint32_t& r3,
                                         uint32_t addr) {
    asm volatile("ldmatrix.sync.aligned.m8n8.x4.trans.shared.b16 {%0,%1,%2,%3}, [%4];"
                 : "=r"(r0), "=r"(r1), "=r"(r2), "=r"(r3) : "r"(addr));
}
__device__ __forceinline__ void mma_f16(float c[4],
    uint32_t a0, uint32_t a1, uint32_t a2, uint32_t a3,
    uint32_t b0, uint32_t b1)
{
    asm volatile(
        "mma.sync.aligned.m16n8k16.row.col.f32.f16.f16.f32 "
        "{%0,%1,%2,%3}, {%4,%5,%6,%7}, {%8,%9}, {%0,%1,%2,%3};"
        : "+f"(c[0]), "+f"(c[1]), "+f"(c[2]), "+f"(c[3])
        : "r"(a0), "r"(a1), "r"(a2), "r"(a3), "r"(b0), "r"(b1));
}
__device__ __forceinline__ void cp16(uint32_t dst, const void* src) {
    asm volatile("cp.async.ca.shared.global [%0], [%1], 16;\n" :: "r"(dst), "l"(src));
}
#define CP_COMMIT() asm volatile("cp.async.commit_group;\n" ::: "memory")
#define CP_WAIT2()  asm volatile("cp.async.wait_group 2;\n" ::: "memory")

// ---------------- gathered expert GEMM (fp16, occupancy-2) ------------------
// BM=128, BN=128, BK=32, 4-stage cp.async; 8 warps (2m x 4n), warp tile 64x32.
// 1D grid. fc1 carries a cvt-w2 tail (blocks beyond the GEMM range convert w2).
#define BM 128
#define BN 128
#define BK 32
#define MT 16
#define AST 40
#define BST 136
#define NSTG 4
#define A_STG (BM * AST)                 // 5120 halfs
#define B_STG (BK * BST)                 // 4352 halfs
#define STG_H (A_STG + B_STG)            // 9472 halfs
#define GEMM_SMEM (NSTG * STG_H * 2 + BM * 4)   // ~76.3 KB
#define CVT2_BLKS (WQUARTS / (256 * 4))  // 4608

template <int WHICH>
__global__ __launch_bounds__(256, 2) void expert_gemm()
{
    constexpr int KD = WHICH ? HDIM : DDIM;
    constexpr int ND = WHICH ? DDIM : HDIM;
    constexpr int NT = ND / BN;                  // 12 / 6
    constexpr int GEMM_BLKS = NEXP * MT * NT;    // 3072 / 1536

    // ---- cvt-w2 tail (fc1 only) ----
    if (WHICH == 0 && blockIdx.x >= GEMM_BLKS) {
        int base = (blockIdx.x - GEMM_BLKS) * 1024 + threadIdx.x;
#pragma unroll
        for (int it = 0; it < 4; it++) {
            int i = base + it * 256;
            float4 v = __ldcs((const float4*)g_p[IX_F2W] + i);
            ((uint2*)g_w2h)[i] = f4_to_h4(v);
        }
        return;
    }

    extern __shared__ __half smh[];
    int* s_entry = (int*)(smh + NSTG * STG_H);

    const __half* Asrc = WHICH ? g_hh : g_xh;
    const __half* W    = WHICH ? g_w2h : g_w1h;
    const float*  bias = g_p[WHICH ? IX_F2B : IX_F1B];

    int idx = blockIdx.x;
    int e   = idx / (MT * NT);
    int mt  = (idx / NT) % MT;
    int nt  = idx % NT;
    int cnt = g_ecnt[e];
    int m0  = mt * BM;
    if (m0 >= cnt) return;
    int n0  = nt * BN;

    int tid  = threadIdx.x;
    int lane = tid & 31;
    int wid  = tid >> 5;
    int wm   = wid >> 2;     // 0..1 -> 64 rows
    int wn   = wid & 3;      // 0..3 -> 32 cols each

    if (tid < BM) {
        int gm = m0 + tid;
        s_entry[tid] = (gm < cnt) ? g_elist[e * T_TOK + gm] : -1;
    }
    __syncthreads();

    // ---- cp.async mappings ----
    int a_row0 = tid >> 2;
    int a_row1 = a_row0 + 64;
    int a_j    = (tid & 3) * 8;
    int ent0 = s_entry[a_row0], ent1 = s_entry[a_row1];
    int ar0 = (ent0 >= 0) ? (WHICH ? ent0 : (ent0 >> 2)) : 0;
    int ar1 = (ent1 >= 0) ? (WHICH ? ent1 : (ent1 >> 2)) : 0;
    const __half* aptr0 = Asrc + (size_t)ar0 * KD + a_j;
    const __half* aptr1 = Asrc + (size_t)ar1 * KD + a_j;
    uint32_t aDst0 = (uint32_t)(a_row0 * AST + a_j) * 2;
    uint32_t aDst1 = (uint32_t)(a_row1 * AST + a_j) * 2;
    int b_row0 = tid >> 4;
    int b_row1 = b_row0 + 16;
    int b_j    = (tid & 15) * 8;
    const __half* wbase = W + (size_t)e * KD * ND + n0 + b_j;
    uint32_t bDst0 = (uint32_t)(A_STG + b_row0 * BST + b_j) * 2;
    uint32_t bDst1 = (uint32_t)(A_STG + b_row1 * BST + b_j) * 2;

    uint32_t sbase = (uint32_t)__cvta_generic_to_shared(smh);

    float acc[4][4][4];
#pragma unroll
    for (int i = 0; i < 4; i++)
#pragma unroll
        for (int j = 0; j < 4; j++)
#pragma unroll
            for (int q = 0; q < 4; q++) acc[i][j][q] = 0.f;

    int lr = lane & 15;
    int lc = lane >> 4;
    uint32_t aOff[4];
#pragma unroll
    for (int mf = 0; mf < 4; mf++)
        aOff[mf] = (uint32_t)(((wm * 64 + mf * 16 + lr) * AST + lc * 8) * 2);
    uint32_t bOff = (uint32_t)((A_STG + lr * BST + wn * 32 + lc * 8) * 2);

    constexpr int nk = KD / BK;   // 24 / 48

    // prologue: stages 0..2
#pragma unroll
    for (int s = 0; s < NSTG - 1; s++) {
        uint32_t st = sbase + (uint32_t)(s * STG_H * 2);
        int k0 = s * BK;
        cp16(st + aDst0, aptr0 + k0);
        cp16(st + aDst1, aptr1 + k0);
        cp16(st + bDst0, wbase + (size_t)(k0 + b_row0) * ND);
        cp16(st + bDst1, wbase + (size_t)(k0 + b_row1) * ND);
        CP_COMMIT();
    }

    for (int kt = 0; kt < nk; kt++) {
        CP_WAIT2();
        __syncthreads();

        int nxt = kt + NSTG - 1;
        if (nxt < nk) {
            uint32_t st = sbase + (uint32_t)((nxt % NSTG) * STG_H * 2);
            int k0 = nxt * BK;
            cp16(st + aDst0, aptr0 + k0);
            cp16(st + aDst1, aptr1 + k0);
            cp16(st + bDst0, wbase + (size_t)(k0 + b_row0) * ND);
            cp16(st + bDst1, wbase + (size_t)(k0 + b_row1) * ND);
        }
        CP_COMMIT();

        uint32_t stg = sbase + (uint32_t)((kt % NSTG) * STG_H * 2);

#pragma unroll
        for (int ks = 0; ks < 2; ks++) {
            uint32_t a[4][4];
#pragma unroll
            for (int mf = 0; mf < 4; mf++)
                ldsm_x4(a[mf][0], a[mf][1], a[mf][2], a[mf][3],
                        stg + aOff[mf] + ks * 32);
            uint32_t b[2][4];
#pragma unroll
            for (int ng = 0; ng < 2; ng++)
                ldsm_x4t(b[ng][0], b[ng][1], b[ng][2], b[ng][3],
                         stg + bOff + (uint32_t)(ks * 16 * BST * 2 + ng * 16 * 2));
#pragma unroll
            for (int mf = 0; mf < 4; mf++)
#pragma unroll
                for (int nf = 0; nf < 4; nf++) {
                    int ng = nf >> 1, hh = (nf & 1) * 2;
                    mma_f16(acc[mf][nf], a[mf][0], a[mf][1], a[mf][2], a[mf][3],
                            b[ng][hh], b[ng][hh + 1]);
                }
        }
    }

    // ---- epilogue ----
    int qrow = lane >> 2;
    int qcol = lane & 3;
    const float* brow = bias + (size_t)e * ND + n0;
#pragma unroll
    for (int mf = 0; mf < 4; mf++) {
        int r0 = wm * 64 + mf * 16 + qrow;
#pragma unroll
        for (int half = 0; half < 2; half++) {
            int r = r0 + half * 8;
            int ent = s_entry[r];
            if (ent < 0) continue;
            if (WHICH == 0) {
                __half* orow = g_hh + (size_t)ent * HDIM + n0;
#pragma unroll
                for (int nf = 0; nf < 4; nf++) {
                    int col = wn * 32 + nf * 8 + qcol * 2;
                    float vx = acc[mf][nf][half * 2 + 0] + brow[col + 0];
                    float vy = acc[mf][nf][half * 2 + 1] + brow[col + 1];
                    *(__half2*)(orow + col) = __floats2half2_rn(vx, vy);
                }
            } else {
                float sc = g_wslot[ent];
                float* orow = g_ybuf + (size_t)ent * DDIM + n0;
#pragma unroll
                for (int nf = 0; nf < 4; nf++) {
                    int col = wn * 32 + nf * 8 + qcol * 2;
                    float2 v;
                    v.x = (acc[mf][nf][half * 2 + 0] + brow[col + 0]) * sc;
                    v.y = (acc[mf][nf][half * 2 + 1] + brow[col + 1]) * sc;
                    *(float2*)(orow + col) = v;
                }
            }
        }
    }
}

// ---------------- exact GELU + LayerNorm (fp16 in/out, in place) ------------
__global__ __launch_bounds__(256) void gelu_ln_kernel()
{
    const float* ln_w = g_p[IX_LNW];
    const float* ln_b = g_p[IX_LNB];

    int slot = blockIdx.x;
    int e = g_eslot[slot];
    __half* h = g_hh + (size_t)slot * HDIM;
    const int PER = HDIM / 256;

    float vals[PER];
    float s = 0.f, s2 = 0.f;
#pragma unroll
    for (int i = 0; i < PER; i++) {
        int j = threadIdx.x + i * 256;
        float v = __half2float(h[j]);
        v = 0.5f * v * (1.0f + erff(v * 0.70710678118654752f));
        vals[i] = v;
        s += v; s2 += v * v;
    }
#pragma unroll
    for (int off = 16; off; off >>= 1) {
        s  += __shfl_xor_sync(0xffffffffu, s,  off);
        s2 += __shfl_xor_sync(0xffffffffu, s2, off);
    }
    __shared__ float shs[8], shs2[8];
    __shared__ float sh_mean, sh_inv;
    int wid = threadIdx.x >> 5, lane = threadIdx.x & 31;
    if (lane == 0) { shs[wid] = s; shs2[wid] = s2; }
    __syncthreads();
    if (threadIdx.x == 0) {
        float ts = 0.f, ts2 = 0.f;
#pragma unroll
        for (int w = 0; w < 8; w++) { ts += shs[w]; ts2 += shs2[w]; }
        float mean = ts * (1.0f / HDIM);
        float var  = ts2 * (1.0f / HDIM) - mean * mean;
        sh_mean = mean;
        sh_inv  = rsqrtf(var + LN_EPS);
    }
    __syncthreads();
    float mean = sh_mean, inv = sh_inv;
    const float* lw = ln_w + (size_t)e * HDIM;
    const float* lb = ln_b + (size_t)e * HDIM;
#pragma unroll
    for (int i = 0; i < PER; i++) {
        int j = threadIdx.x + i * 256;
        float o = (vals[i] - mean) * inv * lw[j] + lb[j];
        h[j] = __float2half_rn(o);
    }
}

// ---------------- combine ----------------
__global__ __launch_bounds__(256) void combine_kernel(float* __restrict__ out)
{
    int i = blockIdx.x * blockDim.x + threadIdx.x;
    if (i >= T_TOK * (DDIM / 4)) return;
    int t = i / (DDIM / 4);
    int j = (i % (DDIM / 4)) * 4;
    const float* yb = g_ybuf + ((size_t)t * NSLOT) * DDIM + j;
    float4 a = *(const float4*)(yb + 0 * DDIM);
    float4 b = *(const float4*)(yb + 1 * DDIM);
    float4 c = *(const float4*)(yb + 2 * DDIM);
    float4 d = *(const float4*)(yb + 3 * DDIM);
    float4 r;
    r.x = a.x + b.x + c.x + d.x;
    r.y = a.y + b.y + c.y + d.y;
    r.z = a.z + b.z + c.z + d.z;
    r.w = a.w + b.w + c.w + d.w;
    *(float4*)(out + (size_t)t * DDIM + j) = r;
}

// ---------------- launch ----------------
extern "C" void kernel_launch(void* const* d_in, const int* in_sizes, int n_in,
                              void* d_out, int out_size)
{
    InArgs a;
    int n = n_in < 9 ? n_in : 9;
    for (int i = 0; i < 9; i++) {
        a.p[i]  = (i < n) ? (const float*)d_in[i] : (const float*)d_in[n - 1];
        a.sz[i] = (i < n) ? in_sizes[i] : 0;
    }
    a.n = n;
    float* out = (float*)d_out;

    cudaFuncSetAttribute(expert_gemm<0>,
                         cudaFuncAttributeMaxDynamicSharedMemorySize, GEMM_SMEM);
    cudaFuncSetAttribute(expert_gemm<1>,
                         cudaFuncAttributeMaxDynamicSharedMemorySize, GEMM_SMEM);

    classify_kernel<<<1, 32>>>(a);
    gate_cvt_kernel<<<GATE_BLKS + CVT1_BLKS + CVTX_BLKS, 256>>>();

    // fc1 (GEMM blocks) + cvt-w2 tail in one launch
    expert_gemm<0><<<NEXP * MT * (HDIM / BN) + CVT2_BLKS, 256, GEMM_SMEM>>>();
    gelu_ln_kernel<<<TOTSLOT, 256>>>();
    expert_gemm<1><<<NEXP * MT * (DDIM / BN), 256, GEMM_SMEM>>>();
    combine_kernel<<<(T_TOK * (DDIM / 4) + 255) / 256, 256>>>(out);
}

// round 15
// speedup vs baseline: 1.1169x; 1.1169x over previous
#include <cuda_runtime.h>
#include <cuda_fp16.h>
#include <math.h>
#include <stdint.h>

// ---------------- problem constants ----------------
#define T_TOK   2048
#define DDIM    768
#define HDIM    1536
#define NEXP    16
#define NSLOT   4
#define TOTSLOT (T_TOK*NSLOT)
#define LN_EPS  1e-5f

#define IX_X    0
#define IX_GW   1
#define IX_GB   2
#define IX_F1W  3
#define IX_F1B  4
#define IX_LNW  5
#define IX_LNB  6
#define IX_F2W  7
#define IX_F2B  8

// ---------------- device scratch ----------------
__device__ const float* g_p[9];
__device__ int   g_ecnt[NEXP];
__device__ int   g_elist[NEXP * T_TOK];
__device__ __align__(16) float  g_wslot[TOTSLOT];
__device__ int   g_eslot[TOTSLOT];
__device__ __align__(16) __half g_hh[(size_t)TOTSLOT * HDIM];            // fc1 out / LN out (fp16)
__device__ __align__(16) float  g_ybuf[(size_t)TOTSLOT * DDIM];          // fc2 out fp32
__device__ __align__(16) __half g_xh[(size_t)T_TOK * DDIM];              // x fp16
__device__ __align__(16) __half g_w1h[(size_t)NEXP * DDIM * HDIM];
__device__ __align__(16) __half g_w2h[(size_t)NEXP * HDIM * DDIM];

struct InArgs { const float* p[9]; int sz[9]; int n; };

#define WQUARTS (NEXP * DDIM * HDIM / 4)      // 4,718,592 float4s per weight
#define XQUARTS (T_TOK * DDIM / 4)            // 393,216

__device__ __forceinline__ uint2 f4_to_h4(float4 v) {
    __half2 lo = __floats2half2_rn(v.x, v.y);
    __half2 hi = __floats2half2_rn(v.z, v.w);
    return make_uint2(*(uint32_t*)&lo, *(uint32_t*)&hi);
}

// ---------------- classify inputs (warp-parallel value scans) ----------------
__global__ void classify_kernel(InArgs a) {
    int lane = threadIdx.x;
    if (lane < NEXP) g_ecnt[lane] = 0;

    __shared__ int nzf[9], onesf[9];
    for (int i = 0; i < 9; i++) {
        bool nz = false, ones = true;
        if (i < a.n) {
            for (int j = lane; j < 256; j += 32)
                if (a.p[i][j] != 0.f) { nz = true; break; }
            for (int j = lane; j < 64; j += 32)
                if (a.p[i][j] != 1.0f) { ones = false; break; }
        }
        unsigned nzb = __ballot_sync(0xffffffffu, nz);
        unsigned onb = __ballot_sync(0xffffffffu, !ones);
        if (lane == 0) { nzf[i] = (nzb != 0); onesf[i] = (onb == 0); }
    }
    __syncwarp();
    if (lane != 0) return;

    bool used[9]; const float* P[9];
#pragma unroll
    for (int i = 0; i < 9; i++) { used[i] = false; P[i] = nullptr; }

    for (int i = 0; i < a.n && i < 9; i++) {
        if (a.sz[i] == T_TOK * DDIM)      { P[IX_X]  = a.p[i]; used[i] = true; }
        else if (a.sz[i] == NEXP)         { P[IX_GB] = a.p[i]; used[i] = true; }
    }
    for (int i = 0; i < a.n && i < 9; i++) {
        if (!used[i] && a.sz[i] == NEXP * DDIM * HDIM) {
            if (!P[IX_F1W]) P[IX_F1W] = a.p[i]; else P[IX_F2W] = a.p[i];
            used[i] = true;
        }
    }
    for (int i = 0; i < a.n && i < 9; i++) {
        if (!used[i] && a.sz[i] == DDIM * NEXP) {
            if (nzf[i] && !P[IX_GW]) P[IX_GW] = a.p[i];
            else if (!P[IX_F2B])     P[IX_F2B] = a.p[i];
            else                     P[IX_GW]  = a.p[i];
            used[i] = true;
        }
    }
    for (int i = 0; i < a.n && i < 9; i++) {
        if (!used[i] && a.sz[i] == NEXP * HDIM) {
            if (onesf[i] && !P[IX_LNW]) P[IX_LNW] = a.p[i];
            else if (!P[IX_F1B])        P[IX_F1B] = a.p[i];
            else if (!P[IX_LNB])        P[IX_LNB] = a.p[i];
            else                        P[IX_LNW] = a.p[i];
            used[i] = true;
        }
    }
#pragma unroll
    for (int k = 0; k < 9; k++) if (!P[k]) P[k] = a.p[k];
#pragma unroll
    for (int k = 0; k < 9; k++) g_p[k] = P[k];
}

// ---------------- fused gating + cvt(w1, w2, x) ------------------------------
// blocks [0, GATE_BLKS): gating (one warp per token)
// then: w1 cvt (CVTW_BLKS), w2 cvt (CVTW_BLKS), x cvt (CVTX_BLKS)
#define GATE_BLKS 256
#define CVTW_BLKS (WQUARTS / (256 * 4))       // 4608 per weight tensor
#define CVTX_BLKS (XQUARTS / (256 * 4))       // 384
#define GC_GRID   (GATE_BLKS + 2 * CVTW_BLKS + CVTX_BLKS)

__global__ __launch_bounds__(256) void gate_cvt_kernel()
{
    if (blockIdx.x >= GATE_BLKS) {
        int cb = blockIdx.x - GATE_BLKS;
        if (cb < CVTW_BLKS) {
            int base = cb * 1024 + threadIdx.x;
#pragma unroll
            for (int it = 0; it < 4; it++) {
                int i = base + it * 256;
                float4 v = __ldcs((const float4*)g_p[IX_F1W] + i);
                ((uint2*)g_w1h)[i] = f4_to_h4(v);
            }
        } else if (cb < 2 * CVTW_BLKS) {
            int base = (cb - CVTW_BLKS) * 1024 + threadIdx.x;
#pragma unroll
            for (int it = 0; it < 4; it++) {
                int i = base + it * 256;
                float4 v = __ldcs((const float4*)g_p[IX_F2W] + i);
                ((uint2*)g_w2h)[i] = f4_to_h4(v);
            }
        } else {
            int base = (cb - 2 * CVTW_BLKS) * 1024 + threadIdx.x;
#pragma unroll
            for (int it = 0; it < 4; it++) {
                int i = base + it * 256;
                float4 v = ((const float4*)g_p[IX_X])[i];
                ((uint2*)g_xh)[i] = f4_to_h4(v);
            }
        }
        return;
    }

    const float* x  = g_p[IX_X];
    const float* gw = g_p[IX_GW];
    const float* gb = g_p[IX_GB];

    int gtid = blockIdx.x * blockDim.x + threadIdx.x;
    int t    = gtid >> 5;
    int lane = gtid & 31;
    if (t >= T_TOK) return;

    float acc[NEXP];
#pragma unroll
    for (int e = 0; e < NEXP; e++) acc[e] = 0.f;

    const float* xr = x + (size_t)t * DDIM;
    for (int d = lane; d < DDIM; d += 32) {
        float xv = xr[d];
        const float* wr = gw + d * NEXP;
#pragma unroll
        for (int e = 0; e < NEXP; e++) acc[e] += xv * wr[e];
    }
#pragma unroll
    for (int e = 0; e < NEXP; e++) {
#pragma unroll
        for (int off = 16; off; off >>= 1)
            acc[e] += __shfl_xor_sync(0xffffffffu, acc[e], off);
    }

    if (lane == 0) {
        float s[NEXP];
#pragma unroll
        for (int e = 0; e < NEXP; e++) s[e] = acc[e] + gb[e];
        s[0] = -1e9f;
        float mx = s[0];
#pragma unroll
        for (int e = 1; e < NEXP; e++) mx = fmaxf(mx, s[e]);
        float p[NEXP]; float sum = 0.f;
#pragma unroll
        for (int e = 0; e < NEXP; e++) { p[e] = expf(s[e] - mx); sum += p[e]; }
        float inv = 1.f / sum;
#pragma unroll
        for (int e = 0; e < NEXP; e++) p[e] *= inv;

        int base = t * NSLOT;
        g_wslot[base] = 1.0f;
        g_eslot[base] = 0;
        int pos = atomicAdd(&g_ecnt[0], 1);
        g_elist[0 * T_TOK + pos] = base;

        for (int k = 0; k < 3; k++) {
            int bi = -1; float bv = -1.f;
#pragma unroll
            for (int e = 0; e < NEXP; e++)
                if (p[e] > bv) { bv = p[e]; bi = e; }
            p[bi] = -2.f;
            g_wslot[base + 1 + k] = bv;
            g_eslot[base + 1 + k] = bi;
            int pp = atomicAdd(&g_ecnt[bi], 1);
            g_elist[bi * T_TOK + pp] = base + 1 + k;
        }
    }
}

// ---------------- fp16 MMA helpers ----------------
__device__ __forceinline__ void ldsm_x4(uint32_t& r0, uint32_t& r1, uint32_t& r2, uint32_t& r3,
                                        uint32_t addr) {
    asm volatile("ldmatrix.sync.aligned.m8n8.x4.shared.b16 {%0,%1,%2,%3}, [%4];"
                 : "=r"(r0), "=r"(r1), "=r"(r2), "=r"(r3) : "r"(addr));
}
__device__ __forceinline__ void ldsm_x4t(uint32_t& r0, uint32_t& r1, uint32_t& r2, uint32_t& r3,
                                         uint32_t addr) {
    asm volatile("ldmatrix.sync.aligned.m8n8.x4.trans.shared.b16 {%0,%1,%2,%3}, [%4];"
                 : "=r"(r0), "=r"(r1), "=r"(r2), "=r"(r3) : "r"(addr));
}
__device__ __forceinline__ void mma_f16(float c[4],
    uint32_t a0, uint32_t a1, uint32_t a2, uint32_t a3,
    uint32_t b0, uint32_t b1)
{
    asm volatile(
        "mma.sync.aligned.m16n8k16.row.col.f32.f16.f16.f32 "
        "{%0,%1,%2,%3}, {%4,%5,%6,%7}, {%8,%9}, {%0,%1,%2,%3};"
        : "+f"(c[0]), "+f"(c[1]), "+f"(c[2]), "+f"(c[3])
        : "r"(a0), "r"(a1), "r"(a2), "r"(a3), "r"(b0), "r"(b1));
}
__device__ __forceinline__ void cp16(uint32_t dst, const void* src) {
    asm volatile("cp.async.ca.shared.global [%0], [%1], 16;\n" :: "r"(dst), "l"(src));
}
#define CP_COMMIT() asm volatile("cp.async.commit_group;\n" ::: "memory")
#define CP_WAIT2()  asm volatile("cp.async.wait_group 2;\n" ::: "memory")

// ---------------- gathered expert GEMM (fp16, occupancy-2) ------------------
// BM=128, BN=128, BK=32, 4-stage cp.async; 8 warps (2m x 4n), warp tile 64x32.
#define BM 128
#define BN 128
#define BK 32
#define MT 16
#define AST 40
#define BST 136
#define NSTG 4
#define A_STG (BM * AST)                 // 5120 halfs
#define B_STG (BK * BST)                 // 4352 halfs
#define STG_H (A_STG + B_STG)            // 9472 halfs
#define GEMM_SMEM (NSTG * STG_H * 2 + BM * 4)   // ~76.3 KB

template <int WHICH>
__global__ __launch_bounds__(256, 2) void expert_gemm(int mtiles_per_e)
{
    constexpr int KD = WHICH ? HDIM : DDIM;
    constexpr int ND = WHICH ? DDIM : HDIM;

    extern __shared__ __half smh[];
    int* s_entry = (int*)(smh + NSTG * STG_H);

    const __half* Asrc = WHICH ? g_hh : g_xh;
    const __half* W    = WHICH ? g_w2h : g_w1h;
    const float*  bias = g_p[WHICH ? IX_F2B : IX_F1B];

    int e  = blockIdx.x / mtiles_per_e;
    int mt = blockIdx.x % mtiles_per_e;
    int cnt = g_ecnt[e];
    int m0 = mt * BM;
    if (m0 >= cnt) return;
    int n0 = blockIdx.y * BN;

    int tid  = threadIdx.x;
    int lane = tid & 31;
    int wid  = tid >> 5;
    int wm   = wid >> 2;     // 0..1 -> 64 rows
    int wn   = wid & 3;      // 0..3 -> 32 cols each

    if (tid < BM) {
        int gm = m0 + tid;
        s_entry[tid] = (gm < cnt) ? g_elist[e * T_TOK + gm] : -1;
    }
    __syncthreads();

    // ---- cp.async mappings ----
    int a_row0 = tid >> 2;
    int a_row1 = a_row0 + 64;
    int a_j    = (tid & 3) * 8;
    int ent0 = s_entry[a_row0], ent1 = s_entry[a_row1];
    int ar0 = (ent0 >= 0) ? (WHICH ? ent0 : (ent0 >> 2)) : 0;
    int ar1 = (ent1 >= 0) ? (WHICH ? ent1 : (ent1 >> 2)) : 0;
    const __half* aptr0 = Asrc + (size_t)ar0 * KD + a_j;
    const __half* aptr1 = Asrc + (size_t)ar1 * KD + a_j;
    uint32_t aDst0 = (uint32_t)(a_row0 * AST + a_j) * 2;
    uint32_t aDst1 = (uint32_t)(a_row1 * AST + a_j) * 2;
    int b_row0 = tid >> 4;
    int b_row1 = b_row0 + 16;
    int b_j    = (tid & 15) * 8;
    const __half* wbase = W + (size_t)e * KD * ND + n0 + b_j;
    uint32_t bDst0 = (uint32_t)(A_STG + b_row0 * BST + b_j) * 2;
    uint32_t bDst1 = (uint32_t)(A_STG + b_row1 * BST + b_j) * 2;

    uint32_t sbase = (uint32_t)__cvta_generic_to_shared(smh);

    float acc[4][4][4];
#pragma unroll
    for (int i = 0; i < 4; i++)
#pragma unroll
        for (int j = 0; j < 4; j++)
#pragma unroll
            for (int q = 0; q < 4; q++) acc[i][j][q] = 0.f;

    int lr = lane & 15;
    int lc = lane >> 4;
    uint32_t aOff[4];
#pragma unroll
    for (int mf = 0; mf < 4; mf++)
        aOff[mf] = (uint32_t)(((wm * 64 + mf * 16 + lr) * AST + lc * 8) * 2);
    uint32_t bOff = (uint32_t)((A_STG + lr * BST + wn * 32 + lc * 8) * 2);

    constexpr int nk = KD / BK;   // 24 / 48

    // prologue: stages 0..2
#pragma unroll
    for (int s = 0; s < NSTG - 1; s++) {
        uint32_t st = sbase + (uint32_t)(s * STG_H * 2);
        int k0 = s * BK;
        cp16(st + aDst0, aptr0 + k0);
        cp16(st + aDst1, aptr1 + k0);
        cp16(st + bDst0, wbase + (size_t)(k0 + b_row0) * ND);
        cp16(st + bDst1, wbase + (size_t)(k0 + b_row1) * ND);
        CP_COMMIT();
    }

    for (int kt = 0; kt < nk; kt++) {
        CP_WAIT2();
        __syncthreads();

        int nxt = kt + NSTG - 1;
        if (nxt < nk) {
            uint32_t st = sbase + (uint32_t)((nxt % NSTG) * STG_H * 2);
            int k0 = nxt * BK;
            cp16(st + aDst0, aptr0 + k0);
            cp16(st + aDst1, aptr1 + k0);
            cp16(st + bDst0, wbase + (size_t)(k0 + b_row0) * ND);
            cp16(st + bDst1, wbase + (size_t)(k0 + b_row1) * ND);
        }
        CP_COMMIT();

        uint32_t stg = sbase + (uint32_t)((kt % NSTG) * STG_H * 2);

#pragma unroll
        for (int ks = 0; ks < 2; ks++) {
            uint32_t a[4][4];
#pragma unroll
            for (int mf = 0; mf < 4; mf++)
                ldsm_x4(a[mf][0], a[mf][1], a[mf][2], a[mf][3],
                        stg + aOff[mf] + ks * 32);
            uint32_t b[2][4];
#pragma unroll
            for (int ng = 0; ng < 2; ng++)
                ldsm_x4t(b[ng][0], b[ng][1], b[ng][2], b[ng][3],
                         stg + bOff + (uint32_t)(ks * 16 * BST * 2 + ng * 16 * 2));
#pragma unroll
            for (int mf = 0; mf < 4; mf++)
#pragma unroll
                for (int nf = 0; nf < 4; nf++) {
                    int ng = nf >> 1, hh = (nf & 1) * 2;
                    mma_f16(acc[mf][nf], a[mf][0], a[mf][1], a[mf][2], a[mf][3],
                            b[ng][hh], b[ng][hh + 1]);
                }
        }
    }

    // ---- epilogue ----
    int qrow = lane >> 2;
    int qcol = lane & 3;
    const float* brow = bias + (size_t)e * ND + n0;
#pragma unroll
    for (int mf = 0; mf < 4; mf++) {
        int r0 = wm * 64 + mf * 16 + qrow;
#pragma unroll
        for (int half = 0; half < 2; half++) {
            int r = r0 + half * 8;
            int ent = s_entry[r];
            if (ent < 0) continue;
            if (WHICH == 0) {
                __half* orow = g_hh + (size_t)ent * HDIM + n0;
#pragma unroll
                for (int nf = 0; nf < 4; nf++) {
                    int col = wn * 32 + nf * 8 + qcol * 2;
                    float vx = acc[mf][nf][half * 2 + 0] + brow[col + 0];
                    float vy = acc[mf][nf][half * 2 + 1] + brow[col + 1];
                    *(__half2*)(orow + col) = __floats2half2_rn(vx, vy);
                }
            } else {
                float sc = g_wslot[ent];
                float* orow = g_ybuf + (size_t)ent * DDIM + n0;
#pragma unroll
                for (int nf = 0; nf < 4; nf++) {
                    int col = wn * 32 + nf * 8 + qcol * 2;
                    float2 v;
                    v.x = (acc[mf][nf][half * 2 + 0] + brow[col + 0]) * sc;
                    v.y = (acc[mf][nf][half * 2 + 1] + brow[col + 1]) * sc;
                    *(float2*)(orow + col) = v;
                }
            }
        }
    }
}

// ---------------- exact GELU + LayerNorm (fp16 in/out, in place) ------------
__global__ __launch_bounds__(256) void gelu_ln_kernel()
{
    const float* ln_w = g_p[IX_LNW];
    const float* ln_b = g_p[IX_LNB];

    int slot = blockIdx.x;
    int e = g_eslot[slot];
    __half* h = g_hh + (size_t)slot * HDIM;
    const int PER = HDIM / 256;

    float vals[PER];
    float s = 0.f, s2 = 0.f;
#pragma unroll
    for (int i = 0; i < PER; i++) {
        int j = threadIdx.x + i * 256;
        float v = __half2float(h[j]);
        v = 0.5f * v * (1.0f + erff(v * 0.70710678118654752f));
        vals[i] = v;
        s += v; s2 += v * v;
    }
#pragma unroll
    for (int off = 16; off; off >>= 1) {
        s  += __shfl_xor_sync(0xffffffffu, s,  off);
        s2 += __shfl_xor_sync(0xffffffffu, s2, off);
    }
    __shared__ float shs[8], shs2[8];
    __shared__ float sh_mean, sh_inv;
    int wid = threadIdx.x >> 5, lane = threadIdx.x & 31;
    if (lane == 0) { shs[wid] = s; shs2[wid] = s2; }
    __syncthreads();
    if (threadIdx.x == 0) {
        float ts = 0.f, ts2 = 0.f;
#pragma unroll
        for (int w = 0; w < 8; w++) { ts += shs[w]; ts2 += shs2[w]; }
        float mean = ts * (1.0f / HDIM);
        float var  = ts2 * (1.0f / HDIM) - mean * mean;
        sh_mean = mean;
        sh_inv  = rsqrtf(var + LN_EPS);
    }
    __syncthreads();
    float mean = sh_mean, inv = sh_inv;
    const float* lw = ln_w + (size_t)e * HDIM;
    const float* lb = ln_b + (size_t)e * HDIM;
#pragma unroll
    for (int i = 0; i < PER; i++) {
        int j = threadIdx.x + i * 256;
        float o = (vals[i] - mean) * inv * lw[j] + lb[j];
        h[j] = __float2half_rn(o);
    }
}

// ---------------- combine ----------------
__global__ __launch_bounds__(256) void combine_kernel(float* __restrict__ out)
{
    int i = blockIdx.x * blockDim.x + threadIdx.x;
    if (i >= T_TOK * (DDIM / 4)) return;
    int t = i / (DDIM / 4);
    int j = (i % (DDIM / 4)) * 4;
    const float* yb = g_ybuf + ((size_t)t * NSLOT) * DDIM + j;
    float4 a = *(const float4*)(yb + 0 * DDIM);
    float4 b = *(const float4*)(yb + 1 * DDIM);
    float4 c = *(const float4*)(yb + 2 * DDIM);
    float4 d = *(const float4*)(yb + 3 * DDIM);
    float4 r;
    r.x = a.x + b.x + c.x + d.x;
    r.y = a.y + b.y + c.y + d.y;
    r.z = a.z + b.z + c.z + d.z;
    r.w = a.w + b.w + c.w + d.w;
    *(float4*)(out + (size_t)t * DDIM + j) = r;
}

// ---------------- launch ----------------
extern "C" void kernel_launch(void* const* d_in, const int* in_sizes, int n_in,
                              void* d_out, int out_size)
{
    InArgs a;
    int n = n_in < 9 ? n_in : 9;
    for (int i = 0; i < 9; i++) {
        a.p[i]  = (i < n) ? (const float*)d_in[i] : (const float*)d_in[n - 1];
        a.sz[i] = (i < n) ? in_sizes[i] : 0;
    }
    a.n = n;
    float* out = (float*)d_out;

    cudaFuncSetAttribute(expert_gemm<0>,
                         cudaFuncAttributeMaxDynamicSharedMemorySize, GEMM_SMEM);
    cudaFuncSetAttribute(expert_gemm<1>,
                         cudaFuncAttributeMaxDynamicSharedMemorySize, GEMM_SMEM);

    classify_kernel<<<1, 32>>>(a);
    gate_cvt_kernel<<<GC_GRID, 256>>>();

    expert_gemm<0><<<dim3(NEXP * MT, HDIM / BN), 256, GEMM_SMEM>>>(MT);
    gelu_ln_kernel<<<TOTSLOT, 256>>>();
    expert_gemm<1><<<dim3(NEXP * MT, DDIM / BN), 256, GEMM_SMEM>>>(MT);
    combine_kernel<<<(T_TOK * (DDIM / 4) + 255) / 256, 256>>>(out);
}

// round 16
// speedup vs baseline: 1.1361x; 1.0173x over previous
#include <cuda_runtime.h>
#include <cuda_fp16.h>
#include <math.h>
#include <stdint.h>

// ---------------- problem constants ----------------
#define T_TOK   2048
#define DDIM    768
#define HDIM    1536
#define NEXP    16
#define NSLOT   4
#define TOTSLOT (T_TOK*NSLOT)
#define LN_EPS  1e-5f

#define IX_X    0
#define IX_GW   1
#define IX_GB   2
#define IX_F1W  3
#define IX_F1B  4
#define IX_LNW  5
#define IX_LNB  6
#define IX_F2W  7
#define IX_F2B  8

// ---------------- device scratch ----------------
__device__ const float* g_p[9];
__device__ int   g_ecnt[NEXP];
__device__ int   g_elist[NEXP * T_TOK];
__device__ __align__(16) float  g_wslot[TOTSLOT];
__device__ int   g_eslot[TOTSLOT];
__device__ __align__(16) __half g_hh[(size_t)TOTSLOT * HDIM];            // fc1 out / LN out (fp16)
__device__ __align__(16) float  g_ybuf[(size_t)TOTSLOT * DDIM];          // fc2 out fp32
__device__ __align__(16) __half g_xh[(size_t)T_TOK * DDIM];              // x fp16
__device__ __align__(16) __half g_w1h[(size_t)NEXP * DDIM * HDIM];
__device__ __align__(16) __half g_w2h[(size_t)NEXP * HDIM * DDIM];

struct InArgs { const float* p[9]; int sz[9]; int n; };

#define WQUARTS (NEXP * DDIM * HDIM / 4)      // 4,718,592 float4s per weight
#define XQUARTS (T_TOK * DDIM / 4)            // 393,216

__device__ __forceinline__ uint2 f4_to_h4(float4 v) {
    __half2 lo = __floats2half2_rn(v.x, v.y);
    __half2 hi = __floats2half2_rn(v.z, v.w);
    return make_uint2(*(uint32_t*)&lo, *(uint32_t*)&hi);
}

// ---------------- classify inputs (warp-parallel value scans) ----------------
__global__ void classify_kernel(InArgs a) {
    int lane = threadIdx.x;
    if (lane < NEXP) g_ecnt[lane] = 0;

    __shared__ int nzf[9], onesf[9];
    for (int i = 0; i < 9; i++) {
        bool nz = false, ones = true;
        if (i < a.n) {
            for (int j = lane; j < 256; j += 32)
                if (a.p[i][j] != 0.f) { nz = true; break; }
            for (int j = lane; j < 64; j += 32)
                if (a.p[i][j] != 1.0f) { ones = false; break; }
        }
        unsigned nzb = __ballot_sync(0xffffffffu, nz);
        unsigned onb = __ballot_sync(0xffffffffu, !ones);
        if (lane == 0) { nzf[i] = (nzb != 0); onesf[i] = (onb == 0); }
    }
    __syncwarp();
    if (lane != 0) return;

    bool used[9]; const float* P[9];
#pragma unroll
    for (int i = 0; i < 9; i++) { used[i] = false; P[i] = nullptr; }

    for (int i = 0; i < a.n && i < 9; i++) {
        if (a.sz[i] == T_TOK * DDIM)      { P[IX_X]  = a.p[i]; used[i] = true; }
        else if (a.sz[i] == NEXP)         { P[IX_GB] = a.p[i]; used[i] = true; }
    }
    for (int i = 0; i < a.n && i < 9; i++) {
        if (!used[i] && a.sz[i] == NEXP * DDIM * HDIM) {
            if (!P[IX_F1W]) P[IX_F1W] = a.p[i]; else P[IX_F2W] = a.p[i];
            used[i] = true;
        }
    }
    for (int i = 0; i < a.n && i < 9; i++) {
        if (!used[i] && a.sz[i] == DDIM * NEXP) {
            if (nzf[i] && !P[IX_GW]) P[IX_GW] = a.p[i];
            else if (!P[IX_F2B])     P[IX_F2B] = a.p[i];
            else                     P[IX_GW]  = a.p[i];
            used[i] = true;
        }
    }
    for (int i = 0; i < a.n && i < 9; i++) {
        if (!used[i] && a.sz[i] == NEXP * HDIM) {
            if (onesf[i] && !P[IX_LNW]) P[IX_LNW] = a.p[i];
            else if (!P[IX_F1B])        P[IX_F1B] = a.p[i];
            else if (!P[IX_LNB])        P[IX_LNB] = a.p[i];
            else                        P[IX_LNW] = a.p[i];
            used[i] = true;
        }
    }
#pragma unroll
    for (int k = 0; k < 9; k++) if (!P[k]) P[k] = a.p[k];
#pragma unroll
    for (int k = 0; k < 9; k++) g_p[k] = P[k];
}

// ---------------- fused gating + cvt(w1, w2, x) ------------------------------
#define GATE_BLKS 256
#define CVTW_BLKS (WQUARTS / (256 * 4))       // 4608 per weight tensor
#define CVTX_BLKS (XQUARTS / (256 * 4))       // 384
#define GC_GRID   (GATE_BLKS + 2 * CVTW_BLKS + CVTX_BLKS)

__global__ __launch_bounds__(256) void gate_cvt_kernel()
{
    if (blockIdx.x >= GATE_BLKS) {
        int cb = blockIdx.x - GATE_BLKS;
        if (cb < CVTW_BLKS) {
            int base = cb * 1024 + threadIdx.x;
#pragma unroll
            for (int it = 0; it < 4; it++) {
                int i = base + it * 256;
                float4 v = __ldcs((const float4*)g_p[IX_F1W] + i);
                ((uint2*)g_w1h)[i] = f4_to_h4(v);
            }
        } else if (cb < 2 * CVTW_BLKS) {
            int base = (cb - CVTW_BLKS) * 1024 + threadIdx.x;
#pragma unroll
            for (int it = 0; it < 4; it++) {
                int i = base + it * 256;
                float4 v = __ldcs((const float4*)g_p[IX_F2W] + i);
                ((uint2*)g_w2h)[i] = f4_to_h4(v);
            }
        } else {
            int base = (cb - 2 * CVTW_BLKS) * 1024 + threadIdx.x;
#pragma unroll
            for (int it = 0; it < 4; it++) {
                int i = base + it * 256;
                float4 v = ((const float4*)g_p[IX_X])[i];
                ((uint2*)g_xh)[i] = f4_to_h4(v);
            }
        }
        return;
    }

    const float* x  = g_p[IX_X];
    const float* gw = g_p[IX_GW];
    const float* gb = g_p[IX_GB];

    int gtid = blockIdx.x * blockDim.x + threadIdx.x;
    int t    = gtid >> 5;
    int lane = gtid & 31;
    if (t >= T_TOK) return;

    float acc[NEXP];
#pragma unroll
    for (int e = 0; e < NEXP; e++) acc[e] = 0.f;

    const float* xr = x + (size_t)t * DDIM;
    for (int d = lane; d < DDIM; d += 32) {
        float xv = xr[d];
        const float* wr = gw + d * NEXP;
#pragma unroll
        for (int e = 0; e < NEXP; e++) acc[e] += xv * wr[e];
    }
#pragma unroll
    for (int e = 0; e < NEXP; e++) {
#pragma unroll
        for (int off = 16; off; off >>= 1)
            acc[e] += __shfl_xor_sync(0xffffffffu, acc[e], off);
    }

    if (lane == 0) {
        float s[NEXP];
#pragma unroll
        for (int e = 0; e < NEXP; e++) s[e] = acc[e] + gb[e];
        s[0] = -1e9f;
        float mx = s[0];
#pragma unroll
        for (int e = 1; e < NEXP; e++) mx = fmaxf(mx, s[e]);
        float p[NEXP]; float sum = 0.f;
#pragma unroll
        for (int e = 0; e < NEXP; e++) { p[e] = expf(s[e] - mx); sum += p[e]; }
        float inv = 1.f / sum;
#pragma unroll
        for (int e = 0; e < NEXP; e++) p[e] *= inv;

        int base = t * NSLOT;
        g_wslot[base] = 1.0f;
        g_eslot[base] = 0;
        int pos = atomicAdd(&g_ecnt[0], 1);
        g_elist[0 * T_TOK + pos] = base;

        for (int k = 0; k < 3; k++) {
            int bi = -1; float bv = -1.f;
#pragma unroll
            for (int e = 0; e < NEXP; e++)
                if (p[e] > bv) { bv = p[e]; bi = e; }
            p[bi] = -2.f;
            g_wslot[base + 1 + k] = bv;
            g_eslot[base + 1 + k] = bi;
            int pp = atomicAdd(&g_ecnt[bi], 1);
            g_elist[bi * T_TOK + pp] = base + 1 + k;
        }
    }
}

// ---------------- fp16 MMA helpers ----------------
__device__ __forceinline__ void ldsm_x4(uint32_t& r0, uint32_t& r1, uint32_t& r2, uint32_t& r3,
                                        uint32_t addr) {
    asm volatile("ldmatrix.sync.aligned.m8n8.x4.shared.b16 {%0,%1,%2,%3}, [%4];"
                 : "=r"(r0), "=r"(r1), "=r"(r2), "=r"(r3) : "r"(addr));
}
__device__ __forceinline__ void ldsm_x4t(uint32_t& r0, uint32_t& r1, uint32_t& r2, uint32_t& r3,
                                         uint32_t addr) {
    asm volatile("ldmatrix.sync.aligned.m8n8.x4.trans.shared.b16 {%0,%1,%2,%3}, [%4];"
                 : "=r"(r0), "=r"(r1), "=r"(r2), "=r"(r3) : "r"(addr));
}
__device__ __forceinline__ void mma_f16(float c[4],
    uint32_t a0, uint32_t a1, uint32_t a2, uint32_t a3,
    uint32_t b0, uint32_t b1)
{
    asm volatile(
        "mma.sync.aligned.m16n8k16.row.col.f32.f16.f16.f32 "
        "{%0,%1,%2,%3}, {%4,%5,%6,%7}, {%8,%9}, {%0,%1,%2,%3};"
        : "+f"(c[0]), "+f"(c[1]), "+f"(c[2]), "+f"(c[3])
        : "r"(a0), "r"(a1), "r"(a2), "r"(a3), "r"(b0), "r"(b1));
}
__device__ __forceinline__ void cp16(uint32_t dst, const void* src) {
    asm volatile("cp.async.ca.shared.global [%0], [%1], 16;\n" :: "r"(dst), "l"(src));
}
#define CP_COMMIT() asm volatile("cp.async.commit_group;\n" ::: "memory")
#define CP_WAIT2()  asm volatile("cp.async.wait_group 2;\n" ::: "memory")

// ---------------- gathered expert GEMM (fp16, occupancy-2) ------------------
// BM=128, BN=128, BK=32, 4-stage cp.async; 8 warps (2m x 4n), warp tile 64x32.
#define BM 128
#define BN 128
#define BK 32
#define MT 16
#define AST 40
#define BST 136
#define NSTG 4
#define A_STG (BM * AST)                 // 5120 halfs
#define B_STG (BK * BST)                 // 4352 halfs
#define STG_H (A_STG + B_STG)            // 9472 halfs
#define GEMM_SMEM (NSTG * STG_H * 2 + BM * 4)   // ~76.3 KB

template <int WHICH>
__global__ __launch_bounds__(256, 2) void expert_gemm(int mtiles_per_e)
{
    constexpr int KD = WHICH ? HDIM : DDIM;
    constexpr int ND = WHICH ? DDIM : HDIM;

    extern __shared__ __half smh[];
    int* s_entry = (int*)(smh + NSTG * STG_H);

    const __half* Asrc = WHICH ? g_hh : g_xh;
    const __half* W    = WHICH ? g_w2h : g_w1h;
    const float*  bias = g_p[WHICH ? IX_F2B : IX_F1B];

    int e  = blockIdx.x / mtiles_per_e;
    int mt = blockIdx.x % mtiles_per_e;
    int cnt = g_ecnt[e];
    int m0 = mt * BM;
    if (m0 >= cnt) return;
    int n0 = blockIdx.y * BN;

    int tid  = threadIdx.x;
    int lane = tid & 31;
    int wid  = tid >> 5;
    int wm   = wid >> 2;     // 0..1 -> 64 rows
    int wn   = wid & 3;      // 0..3 -> 32 cols each

    if (tid < BM) {
        int gm = m0 + tid;
        s_entry[tid] = (gm < cnt) ? g_elist[e * T_TOK + gm] : -1;
    }
    __syncthreads();

    // ---- cp.async mappings ----
    int a_row0 = tid >> 2;
    int a_row1 = a_row0 + 64;
    int a_j    = (tid & 3) * 8;
    int ent0 = s_entry[a_row0], ent1 = s_entry[a_row1];
    int ar0 = (ent0 >= 0) ? (WHICH ? ent0 : (ent0 >> 2)) : 0;
    int ar1 = (ent1 >= 0) ? (WHICH ? ent1 : (ent1 >> 2)) : 0;
    const __half* aptr0 = Asrc + (size_t)ar0 * KD + a_j;
    const __half* aptr1 = Asrc + (size_t)ar1 * KD + a_j;
    uint32_t aDst0 = (uint32_t)(a_row0 * AST + a_j) * 2;
    uint32_t aDst1 = (uint32_t)(a_row1 * AST + a_j) * 2;
    int b_row0 = tid >> 4;
    int b_row1 = b_row0 + 16;
    int b_j    = (tid & 15) * 8;
    const __half* wbase = W + (size_t)e * KD * ND + n0 + b_j;
    uint32_t bDst0 = (uint32_t)(A_STG + b_row0 * BST + b_j) * 2;
    uint32_t bDst1 = (uint32_t)(A_STG + b_row1 * BST + b_j) * 2;

    uint32_t sbase = (uint32_t)__cvta_generic_to_shared(smh);

    float acc[4][4][4];
#pragma unroll
    for (int i = 0; i < 4; i++)
#pragma unroll
        for (int j = 0; j < 4; j++)
#pragma unroll
            for (int q = 0; q < 4; q++) acc[i][j][q] = 0.f;

    int lr = lane & 15;
    int lc = lane >> 4;
    uint32_t aOff[4];
#pragma unroll
    for (int mf = 0; mf < 4; mf++)
        aOff[mf] = (uint32_t)(((wm * 64 + mf * 16 + lr) * AST + lc * 8) * 2);
    uint32_t bOff = (uint32_t)((A_STG + lr * BST + wn * 32 + lc * 8) * 2);

    constexpr int nk = KD / BK;   // 24 / 48

    // prologue: stages 0..2
#pragma unroll
    for (int s = 0; s < NSTG - 1; s++) {
        uint32_t st = sbase + (uint32_t)(s * STG_H * 2);
        int k0 = s * BK;
        cp16(st + aDst0, aptr0 + k0);
        cp16(st + aDst1, aptr1 + k0);
        cp16(st + bDst0, wbase + (size_t)(k0 + b_row0) * ND);
        cp16(st + bDst1, wbase + (size_t)(k0 + b_row1) * ND);
        CP_COMMIT();
    }

    for (int kt = 0; kt < nk; kt++) {
        CP_WAIT2();
        __syncthreads();

        int nxt = kt + NSTG - 1;
        if (nxt < nk) {
            uint32_t st = sbase + (uint32_t)((nxt % NSTG) * STG_H * 2);
            int k0 = nxt * BK;
            cp16(st + aDst0, aptr0 + k0);
            cp16(st + aDst1, aptr1 + k0);
            cp16(st + bDst0, wbase + (size_t)(k0 + b_row0) * ND);
            cp16(st + bDst1, wbase + (size_t)(k0 + b_row1) * ND);
        }
        CP_COMMIT();

        uint32_t stg = sbase + (uint32_t)((kt % NSTG) * STG_H * 2);

#pragma unroll
        for (int ks = 0; ks < 2; ks++) {
            uint32_t a[4][4];
#pragma unroll
            for (int mf = 0; mf < 4; mf++)
                ldsm_x4(a[mf][0], a[mf][1], a[mf][2], a[mf][3],
                        stg + aOff[mf] + ks * 32);
            uint32_t b[2][4];
#pragma unroll
            for (int ng = 0; ng < 2; ng++)
                ldsm_x4t(b[ng][0], b[ng][1], b[ng][2], b[ng][3],
                         stg + bOff + (uint32_t)(ks * 16 * BST * 2 + ng * 16 * 2));
#pragma unroll
            for (int mf = 0; mf < 4; mf++)
#pragma unroll
                for (int nf = 0; nf < 4; nf++) {
                    int ng = nf >> 1, hh = (nf & 1) * 2;
                    mma_f16(acc[mf][nf], a[mf][0], a[mf][1], a[mf][2], a[mf][3],
                            b[ng][hh], b[ng][hh + 1]);
                }
        }
    }

    // ---- epilogue ----
    int qrow = lane >> 2;
    int qcol = lane & 3;
    const float* brow = bias + (size_t)e * ND + n0;
#pragma unroll
    for (int mf = 0; mf < 4; mf++) {
        int r0 = wm * 64 + mf * 16 + qrow;
#pragma unroll
        for (int half = 0; half < 2; half++) {
            int r = r0 + half * 8;
            int ent = s_entry[r];
            if (ent < 0) continue;
            if (WHICH == 0) {
                __half* orow = g_hh + (size_t)ent * HDIM + n0;
#pragma unroll
                for (int nf = 0; nf < 4; nf++) {
                    int col = wn * 32 + nf * 8 + qcol * 2;
                    float vx = acc[mf][nf][half * 2 + 0] + brow[col + 0];
                    float vy = acc[mf][nf][half * 2 + 1] + brow[col + 1];
                    *(__half2*)(orow + col) = __floats2half2_rn(vx, vy);
                }
            } else {
                float sc = g_wslot[ent];
                float* orow = g_ybuf + (size_t)ent * DDIM + n0;
#pragma unroll
                for (int nf = 0; nf < 4; nf++) {
                    int col = wn * 32 + nf * 8 + qcol * 2;
                    float2 v;
                    v.x = (acc[mf][nf][half * 2 + 0] + brow[col + 0]) * sc;
                    v.y = (acc[mf][nf][half * 2 + 1] + brow[col + 1]) * sc;
                    *(float2*)(orow + col) = v;
                }
            }
        }
    }
}

// ---------------- fast exact-erf GELU (A&S 7.1.26, |err| < 1.5e-7) ----------
__device__ __forceinline__ float gelu_fast(float x) {
    float z = x * 0.70710678118654752f;
    float s = fabsf(z);
    float k = __fdividef(1.0f, fmaf(0.3275911f, s, 1.0f));
    float poly = k * fmaf(k, fmaf(k, fmaf(k, fmaf(k, 1.061405429f, -1.453152027f),
                                          1.421413741f), -0.284496736f), 0.254829592f);
    float erf_s = 1.0f - poly * __expf(-s * s);
    float erf_z = copysignf(erf_s, z);
    return 0.5f * x * (1.0f + erf_z);
}

// ---------------- GELU + LayerNorm (fp16 in/out, in place, half2 IO) ---------
__global__ __launch_bounds__(256) void gelu_ln_kernel()
{
    const float* ln_w = g_p[IX_LNW];
    const float* ln_b = g_p[IX_LNB];

    int slot = blockIdx.x;
    int e = g_eslot[slot];
    __half2* h2 = (__half2*)(g_hh + (size_t)slot * HDIM);
    const int PER2 = HDIM / 2 / 256;   // 3 half2 per thread

    float2 vals[PER2];
    float s = 0.f, s2 = 0.f;
#pragma unroll
    for (int i = 0; i < PER2; i++) {
        int j = threadIdx.x + i * 256;
        float2 v = __half22float2(h2[j]);
        v.x = gelu_fast(v.x);
        v.y = gelu_fast(v.y);
        vals[i] = v;
        s  += v.x + v.y;
        s2 += v.x * v.x + v.y * v.y;
    }
#pragma unroll
    for (int off = 16; off; off >>= 1) {
        s  += __shfl_xor_sync(0xffffffffu, s,  off);
        s2 += __shfl_xor_sync(0xffffffffu, s2, off);
    }
    __shared__ float shs[8], shs2[8];
    __shared__ float sh_mean, sh_inv;
    int wid = threadIdx.x >> 5, lane = threadIdx.x & 31;
    if (lane == 0) { shs[wid] = s; shs2[wid] = s2; }
    __syncthreads();
    if (threadIdx.x == 0) {
        float ts = 0.f, ts2 = 0.f;
#pragma unroll
        for (int w = 0; w < 8; w++) { ts += shs[w]; ts2 += shs2[w]; }
        float mean = ts * (1.0f / HDIM);
        float var  = ts2 * (1.0f / HDIM) - mean * mean;
        sh_mean = mean;
        sh_inv  = rsqrtf(var + LN_EPS);
    }
    __syncthreads();
    float mean = sh_mean, inv = sh_inv;
    const float2* lw2 = (const float2*)(ln_w + (size_t)e * HDIM);
    const float2* lb2 = (const float2*)(ln_b + (size_t)e * HDIM);
#pragma unroll
    for (int i = 0; i < PER2; i++) {
        int j = threadIdx.x + i * 256;
        float2 w = lw2[j], b = lb2[j];
        float ox = (vals[i].x - mean) * inv * w.x + b.x;
        float oy = (vals[i].y - mean) * inv * w.y + b.y;
        h2[j] = __floats2half2_rn(ox, oy);
    }
}

// ---------------- combine ----------------
__global__ __launch_bounds__(256) void combine_kernel(float* __restrict__ out)
{
    int i = blockIdx.x * blockDim.x + threadIdx.x;
    if (i >= T_TOK * (DDIM / 4)) return;
    int t = i / (DDIM / 4);
    int j = (i % (DDIM / 4)) * 4;
    const float* yb = g_ybuf + ((size_t)t * NSLOT) * DDIM + j;
    float4 a = *(const float4*)(yb + 0 * DDIM);
    float4 b = *(const float4*)(yb + 1 * DDIM);
    float4 c = *(const float4*)(yb + 2 * DDIM);
    float4 d = *(const float4*)(yb + 3 * DDIM);
    float4 r;
    r.x = a.x + b.x + c.x + d.x;
    r.y = a.y + b.y + c.y + d.y;
    r.z = a.z + b.z + c.z + d.z;
    r.w = a.w + b.w + c.w + d.w;
    *(float4*)(out + (size_t)t * DDIM + j) = r;
}

// ---------------- launch ----------------
extern "C" void kernel_launch(void* const* d_in, const int* in_sizes, int n_in,
                              void* d_out, int out_size)
{
    InArgs a;
    int n = n_in < 9 ? n_in : 9;
    for (int i = 0; i < 9; i++) {
        a.p[i]  = (i < n) ? (const float*)d_in[i] : (const float*)d_in[n - 1];
        a.sz[i] = (i < n) ? in_sizes[i] : 0;
    }
    a.n = n;
    float* out = (float*)d_out;

    cudaFuncSetAttribute(expert_gemm<0>,
                         cudaFuncAttributeMaxDynamicSharedMemorySize, GEMM_SMEM);
    cudaFuncSetAttribute(expert_gemm<1>,
                         cudaFuncAttributeMaxDynamicSharedMemorySize, GEMM_SMEM);

    classify_kernel<<<1, 32>>>(a);
    gate_cvt_kernel<<<GC_GRID, 256>>>();

    expert_gemm<0><<<dim3(NEXP * MT, HDIM / BN), 256, GEMM_SMEM>>>(MT);
    gelu_ln_kernel<<<TOTSLOT, 256>>>();
    expert_gemm<1><<<dim3(NEXP * MT, DDIM / BN), 256, GEMM_SMEM>>>(MT);
    combine_kernel<<<(T_TOK * (DDIM / 4) + 255) / 256, 256>>>(out);
}